// round 16
// baseline (speedup 1.0000x reference)
#include <cuda_runtime.h>
#include <math.h>

// Problem constants (fixed by the reference)
#define T  1024
#define B  256
#define H  20
#define OSTRIDE (B * 3)          // 768 floats between consecutive time rows
#define IHP 1060                 // ih row pitch (words): 16B-aligned, %32==4

// Memory kernel me[t] = sigmoid(MLP(t))
__device__ float g_me[T];

// ---------------------------------------------------------------------------
// Kernel 1: tiny MLP over the T time points. One thread per time point.
// ---------------------------------------------------------------------------
__global__ void mlp_kernel(const float* __restrict__ t,
                           const float* __restrict__ w1, const float* __restrict__ b1,
                           const float* __restrict__ w2, const float* __restrict__ b2,
                           const float* __restrict__ w3, const float* __restrict__ b3,
                           const float* __restrict__ w4, const float* __restrict__ b4)
{
    int i = blockIdx.x * blockDim.x + threadIdx.x;
    if (i >= T) return;
    float x = t[i];

    float h1[H], h2[H], h3[H];
#pragma unroll
    for (int j = 0; j < H; ++j) h1[j] = tanhf(x * w1[j] + b1[j]);

#pragma unroll
    for (int j = 0; j < H; ++j) {
        float s = b2[j];
#pragma unroll
        for (int k = 0; k < H; ++k) s += h1[k] * w2[k * H + j];
        h2[j] = tanhf(s);
    }

#pragma unroll
    for (int j = 0; j < H; ++j) {
        float s = b3[j];
#pragma unroll
        for (int k = 0; k < H; ++k) s += h2[k] * w3[k * H + j];
        h3[j] = tanhf(s);
    }

    float s = b4[0];
#pragma unroll
    for (int k = 0; k < H; ++k) s += h3[k] * w4[k];

    g_me[i] = 1.0f / (1.0f + expf(-s));   // sigmoid
}

// ---------------------------------------------------------------------------
// Kernel 2: BATCH-PER-LANE, role-per-SMSP. 2 batches/block, 128 blocks.
// 6 warps (wid%4 -> SMSP):
//   w0 (S0): state warp. Near triangle in registers; per step ONE STS.128
//            publishing {S,I,dS,dI} to a parity pub ring + ihb STS. No STG,
//            no SELs, no R/dR computation (reconstructed by w5).
//   w4 (S0): catchup warp — register taps; fsum = far fold + 32-tap catch-up
//            (8 LDS.128/batch). Releases w0 via named bar.sync 1,64.
//   w1/w2/w3 (S1/S2/S3): merged-batch far dot for chunk c+1 over t<32c.
//   w5 (S1): output warp — flushes chunk c-1 from the pub ring: reconstructs
//            R = tot-S-I, dR = -(dS+dI), does all SEL+scatter-STG work.
// ONE full __syncthreads per chunk.
// ---------------------------------------------------------------------------
__global__ void __launch_bounds__(192, 1)
solver_kernel(const float* __restrict__ t,
              const float* __restrict__ y,
              const float* __restrict__ beta_p,
              const float* __restrict__ gamma_p,
              float* __restrict__ out)
{
    __shared__ __align__(16) float rkp[1056];        // rkp[32+l]=rk[l]; [0..31]=0
    __shared__ __align__(16) float rks4[4][1088];    // rks4[r][i] = rkp[i+r] (0-pad)
    __shared__ __align__(16) float ih[2][IHP];       // per-batch I history
    __shared__ float fb[3][2][32][2];                // far partials [v][parity][s][b]
    __shared__ __align__(16) float fsumP[2][32];     // far+catchup, batch-major
    __shared__ __align__(16) float pub[2][2][32][4]; // {S,I,dS,dI} [b][parity][s]

    const int tid  = threadIdx.x;
    const int w    = tid >> 5;
    const int lane = tid & 31;

    // ---- cooperative init ----
    for (int i = tid; i < 1056; i += 192)
        rkp[i] = (i < 32) ? 0.0f : g_me[T - 1 - (i - 32)];
    for (int i = tid; i < 4 * 1088; i += 192) {
        const int r = i / 1088, j = i - r * 1088, k = j + r;
        (&rks4[0][0])[i] = (k >= 32 && k < 1056) ? g_me[T - 1 - (k - 32)] : 0.0f;
    }
    for (int i = tid; i < 2 * IHP; i += 192) (&ih[0][0])[i] = 0.0f;
    for (int i = tid; i < 384; i += 192) (&fb[0][0][0][0])[i] = 0.0f;

    const float dt    = t[0] - t[1];       // = 1/(T-1), positive
    const float beta  = beta_p[0];
    const float gamma = gamma_p[0];

    const int h  = lane & 1;               // lane's batch slot
    const int bb = blockIdx.x * 2 + h;     // global batch id

    float S = y[bb * 3 + 0];
    float I = y[bb * 3 + 1];
    float R0 = y[bb * 3 + 2];
    const float tot = S + I + R0;          // conserved: dS+dI+dR == 0

    // w5 per-lane scatter-store mapping (lanes 0..11): sub=lane>>1 picks
    // S/I/R/dS/dI/dR, lane&1 picks batch. Solution row for step idx is idx+1
    // (folded +OSTRIDE); diff row is idx.
    const int  sub   = lane >> 1;
    const bool doSt  = (lane < 12);
    const bool isSol = (sub < 3);
    const int  comp  = isSol ? sub : sub - 3;
    const bool cc0 = (comp == 0), cc1 = (comp == 1);
    float* stbase = isSol ? (out + bb * 3 + comp + OSTRIDE)
                          : (out + (size_t)T * OSTRIDE + bb * 3 + comp);

    if (w == 0 && lane < 2) {
        // solution[0] = y0 ; diff[T-1] = 0 (d_out poisoned -> must be written)
        float* p1 = out + bb * 3;
        p1[0] = S; p1[1] = I; p1[2] = R0;
        float* pz = out + (size_t)T * OSTRIDE + (T - 1) * OSTRIDE + bb * 3;
        pz[0] = 0.0f; pz[1] = 0.0f; pz[2] = 0.0f;
    }
    __syncthreads();

    // w0: near taps (uniform scalars). w4: catchup taps.
    float tapc[32];
#pragma unroll
    for (int j = 0; j < 32; ++j) tapc[j] = rkp[32 + j];   // rk[j]
    float ctap[32];
#pragma unroll
    for (int j = 0; j < 32; ++j) ctap[j] = rkp[64 + lane - j];  // rk[lane+32-j]

    float* ihb = ih[h];
    float Iv[32];

    // ------------------- chunks 0..30 (32 steps each) -----------------------
    for (int c = 0; c < 31; ++c) {
        const int base = c << 5;
        const int par  = c & 1;

        if (w == 4) {
            // ---- catchup warp: fsum for both batches (lane = s) ----
#pragma unroll
            for (int bA = 0; bA < 2; ++bA) {
                float c0 = 0.0f, c1 = 0.0f, c2 = 0.0f, c3 = 0.0f;
                if (c > 0) {
                    const float4* i4 = (const float4*)(ih[bA] + base - 32);
#pragma unroll
                    for (int g = 0; g < 8; ++g) {
                        const float4 v = i4[g];
                        c0 = fmaf(ctap[4 * g],     v.x, c0);
                        c1 = fmaf(ctap[4 * g + 1], v.y, c1);
                        c2 = fmaf(ctap[4 * g + 2], v.z, c2);
                        c3 = fmaf(ctap[4 * g + 3], v.w, c3);
                    }
                }
                fsumP[bA][lane] = ((fb[0][par][lane][bA] + fb[1][par][lane][bA])
                                   + fb[2][par][lane][bA]) + ((c0 + c1) + (c2 + c3));
            }
            asm volatile("bar.sync 1, 64;" ::: "memory");   // release w0
        } else if (w == 0) {
            asm volatile("bar.sync 1, 64;" ::: "memory");   // wait for fsum

            // ---- state warp: near chain ----
            const float4* p4 = (const float4*)fsumP[h];     // 2 addrs/warp
            float4 fq0 = p4[0], fq1;
            float4* pubp = (float4*)&pub[h][par][0][0];

#pragma unroll
            for (int s = 0; s < 32; ++s) {
                // double-buffered fsum prefetch (all indices compile-time)
                if ((s & 3) == 0 && s + 4 < 32) {
                    if (((s >> 2) + 1) & 1) fq1 = p4[(s >> 2) + 1];
                    else                    fq0 = p4[(s >> 2) + 1];
                }
                const float4 fc = ((s >> 2) & 1) ? fq1 : fq0;
                const float  fs = ((s & 3) == 0) ? fc.x :
                                  ((s & 3) == 1) ? fc.y :
                                  ((s & 3) == 2) ? fc.z : fc.w;

                Iv[s] = I;
                ihb[base + s] = I;          // all lanes; 2 distinct addrs/warp

                float a0 = fs, a1 = 0.0f, a2 = 0.0f, a3 = 0.0f;
#pragma unroll
                for (int u = 0; u <= s; ++u) {
                    const float p = tapc[s - u];
                    if      ((u & 3) == 0) a0 = fmaf(p, Iv[u], a0);
                    else if ((u & 3) == 1) a1 = fmaf(p, Iv[u], a1);
                    else if ((u & 3) == 2) a2 = fmaf(p, Iv[u], a2);
                    else                   a3 = fmaf(p, Iv[u], a3);
                }

                const float integ = dt * ((a0 + a1) + (a2 + a3));
                const float bSI = beta * S * I;
                const float gI  = gamma * I;
                const float dS  = integ - bSI;
                const float dI  = bSI - gI;
                S = fmaf(dS, dt, S);
                I = fmaf(dI, dt, I);

                pubp[s] = make_float4(S, I, dS, dI);   // 1 STS.128, 2 addrs
            }
        } else if (w == 5) {
            // ---- output warp: flush chunk c-1 from pub ring ----
            if (c >= 1) {
                const int co = c - 1;
                const float4* pv4 = (const float4*)&pub[h][co & 1][0][0];
                float* stc = stbase + (co << 5) * OSTRIDE;
#pragma unroll 4
                for (int s = 0; s < 32; ++s) {
                    const float4 pv = pv4[s];
                    const float Rp = tot - pv.x - pv.y;
                    const float dR = -(pv.z + pv.w);
                    const float vs = cc0 ? pv.x : (cc1 ? pv.y : Rp);
                    const float vd = cc0 ? pv.z : (cc1 ? pv.w : dR);
                    const float vv = isSol ? vs : vd;
                    if (doSt) stc[s * OSTRIDE] = vv;
                }
            }
        } else {
            // ---- far warps w1..w3 (v=w-1): chunk c+1 over t < 32c, MERGED ----
            const int v    = w - 1;
            const int A    = 32 + ((c + 1) << 5) + lane;  // rkp idx for t=0
            const int r    = (A + 1) & 3;
            const int idx0 = (A - 3 - r) >> 2;
            const float4* tp  = (const float4*)rks4[r];
            const float4* i40 = (const float4*)ih[0];
            const float4* i41 = (const float4*)ih[1];

            float p00 = 0.0f, p01 = 0.0f, p02 = 0.0f, p03 = 0.0f;
            float p10 = 0.0f, p11 = 0.0f, p12 = 0.0f, p13 = 0.0f;
            const int ng = c << 3;                        // 8c float4 groups
#pragma unroll 4
            for (int g = v; g < ng; g += 3) {
                const float4 tv = tp[idx0 - g];           // rkp[A-4g-3 .. A-4g]
                const float4 a0 = i40[g];
                const float4 a1 = i41[g];
                p00 = fmaf(tv.w, a0.x, p00);
                p01 = fmaf(tv.z, a0.y, p01);
                p02 = fmaf(tv.y, a0.z, p02);
                p03 = fmaf(tv.x, a0.w, p03);
                p10 = fmaf(tv.w, a1.x, p10);
                p11 = fmaf(tv.z, a1.y, p11);
                p12 = fmaf(tv.y, a1.z, p12);
                p13 = fmaf(tv.x, a1.w, p13);
            }
            const int pnx = (c + 1) & 1;
            fb[v][pnx][lane][0] = (p00 + p01) + (p02 + p03);
            fb[v][pnx][lane][1] = (p10 + p11) + (p12 + p13);
        }
        __syncthreads();   // single full barrier per chunk
    }

    // ------------------- tail chunk c=31: 31 steps --------------------------
    {
        const int base = 31 << 5;   // 992, parity 1
        if (w == 4) {
#pragma unroll
            for (int bA = 0; bA < 2; ++bA) {
                float c0 = 0.0f, c1 = 0.0f, c2 = 0.0f, c3 = 0.0f;
                const float4* i4 = (const float4*)(ih[bA] + base - 32);
#pragma unroll
                for (int g = 0; g < 8; ++g) {
                    const float4 v = i4[g];
                    c0 = fmaf(ctap[4 * g],     v.x, c0);
                    c1 = fmaf(ctap[4 * g + 1], v.y, c1);
                    c2 = fmaf(ctap[4 * g + 2], v.z, c2);
                    c3 = fmaf(ctap[4 * g + 3], v.w, c3);
                }
                fsumP[bA][lane] = ((fb[0][1][lane][bA] + fb[1][1][lane][bA])
                                   + fb[2][1][lane][bA]) + ((c0 + c1) + (c2 + c3));
            }
            asm volatile("bar.sync 1, 64;" ::: "memory");
        } else if (w == 0) {
            asm volatile("bar.sync 1, 64;" ::: "memory");

            const float4* p4 = (const float4*)fsumP[h];
            float4 fq0 = p4[0], fq1;
            float4* pubp = (float4*)&pub[h][1][0][0];

#pragma unroll
            for (int s = 0; s < 31; ++s) {
                if ((s & 3) == 0 && s + 4 < 32) {
                    if (((s >> 2) + 1) & 1) fq1 = p4[(s >> 2) + 1];
                    else                    fq0 = p4[(s >> 2) + 1];
                }
                const float4 fc = ((s >> 2) & 1) ? fq1 : fq0;
                const float  fs = ((s & 3) == 0) ? fc.x :
                                  ((s & 3) == 1) ? fc.y :
                                  ((s & 3) == 2) ? fc.z : fc.w;

                Iv[s] = I;
                float a0 = fs, a1 = 0.0f, a2 = 0.0f, a3 = 0.0f;
#pragma unroll
                for (int u = 0; u <= s; ++u) {
                    const float p = tapc[s - u];
                    if      ((u & 3) == 0) a0 = fmaf(p, Iv[u], a0);
                    else if ((u & 3) == 1) a1 = fmaf(p, Iv[u], a1);
                    else if ((u & 3) == 2) a2 = fmaf(p, Iv[u], a2);
                    else                   a3 = fmaf(p, Iv[u], a3);
                }

                const float integ = dt * ((a0 + a1) + (a2 + a3));
                const float bSI = beta * S * I;
                const float gI  = gamma * I;
                const float dS  = integ - bSI;
                const float dI  = bSI - gI;
                S = fmaf(dS, dt, S);
                I = fmaf(dI, dt, I);

                pubp[s] = make_float4(S, I, dS, dI);
            }
        } else if (w == 5) {
            // flush chunk 30 (parity 0) while the tail runs
            const int co = 30;
            const float4* pv4 = (const float4*)&pub[h][0][0][0];
            float* stc = stbase + (co << 5) * OSTRIDE;
#pragma unroll 4
            for (int s = 0; s < 32; ++s) {
                const float4 pv = pv4[s];
                const float Rp = tot - pv.x - pv.y;
                const float dR = -(pv.z + pv.w);
                const float vs = cc0 ? pv.x : (cc1 ? pv.y : Rp);
                const float vd = cc0 ? pv.z : (cc1 ? pv.w : dR);
                const float vv = isSol ? vs : vd;
                if (doSt) stc[s * OSTRIDE] = vv;
            }
        }
        __syncthreads();

        // epilogue: flush chunk 31 (parity 1, 31 steps)
        if (w == 5) {
            const int co = 31;
            const float4* pv4 = (const float4*)&pub[h][1][0][0];
            float* stc = stbase + (co << 5) * OSTRIDE;
#pragma unroll 4
            for (int s = 0; s < 31; ++s) {
                const float4 pv = pv4[s];
                const float Rp = tot - pv.x - pv.y;
                const float dR = -(pv.z + pv.w);
                const float vs = cc0 ? pv.x : (cc1 ? pv.y : Rp);
                const float vd = cc0 ? pv.z : (cc1 ? pv.w : dR);
                const float vv = isSol ? vs : vd;
                if (doSt) stc[s * OSTRIDE] = vv;
            }
        }
    }
}

// ---------------------------------------------------------------------------
// Launch: two kernels, stream-ordered, graph-capturable, allocation-free.
// Input order (metadata): t, y, w1, b1, w2, b2, w3, b3, w4, b4, beta, gamma
// Output: [solution (T,B,3) | diff (T,B,3)] float32
// ---------------------------------------------------------------------------
extern "C" void kernel_launch(void* const* d_in, const int* in_sizes, int n_in,
                              void* d_out, int out_size)
{
    const float* t  = (const float*)d_in[0];
    const float* y  = (const float*)d_in[1];
    const float* w1 = (const float*)d_in[2];
    const float* b1 = (const float*)d_in[3];
    const float* w2 = (const float*)d_in[4];
    const float* b2 = (const float*)d_in[5];
    const float* w3 = (const float*)d_in[6];
    const float* b3 = (const float*)d_in[7];
    const float* w4 = (const float*)d_in[8];
    const float* b4 = (const float*)d_in[9];
    const float* be = (const float*)d_in[10];
    const float* ga = (const float*)d_in[11];
    float* out = (float*)d_out;

    mlp_kernel<<<4, 256>>>(t, w1, b1, w2, b2, w3, b3, w4, b4);
    solver_kernel<<<B / 2, 192>>>(t, y, be, ga, out);
}